// round 15
// baseline (speedup 1.0000x reference)
#include <cuda_runtime.h>
#include <cuda_fp16.h>
#include <math.h>

// Fixed problem shape: F=200000, B=4, V=100000.
#define FMAX 200000
#define BMAX 4
#define VMAX 100000

// Mixed-precision 64B per-face record (4 uint4 chunks), 128B-array-aligned.
// bytes  0..23 : vt as fp32  [vt0.u vt0.v vt1.u vt1.v vt2.u vt2.v]
// bytes 24..41 : vn as fp16  [vn0.xyz vn1.xyz vn2.xyz]   (half idx 12..20)
// bytes 42..59 : v  as fp16  [v0.xyz  v1.xyz  v2.xyz ]   (half idx 21..29)
// bytes 60..63 : pad                                      (half idx 30..31)
__device__ __align__(128) uint4 g_packed[FMAX * 4];
// Per (b,f): {1/z0, 1/z1, 1/z2, 0} fp32
__device__ float4 g_invfz[BMAX * FMAX];
// fp32-expanded vertex attribute tables (one LDG.128 per gather in pack)
__device__ float4 g_verts4[VMAX];
__device__ float4 g_vns4[VMAX];

// ---------- kernel 1: expand (latency-bound) INTERLEAVED with fz (DRAM) -----
// Independent producers; parity-interleaved so both kinds co-reside from wave 1.
__global__ __launch_bounds__(256) void expand_fz_kernel(
        const float* __restrict__ verts,
        const float* __restrict__ vns,
        const float* __restrict__ fuvz,
        int V, int BF, int blocksE, int blocksFZ) {
    int tid = threadIdx.x;
    int bi  = blockIdx.x;
    int twice = 2 * (blocksE < blocksFZ ? blocksE : blocksFZ);
    bool isExp;
    int idx;
    if (bi < twice) { isExp = !(bi & 1); idx = bi >> 1; }
    else {
        int r = bi - twice;
        if (blocksE > blocksFZ) { isExp = true;  idx = blocksFZ + r; }
        else                    { isExp = false; idx = blocksE  + r; }
    }

    if (isExp) {
        int i = idx * 256 + tid;
        if (i >= V) return;
        g_verts4[i] = make_float4(__ldcs(&verts[3 * i]), __ldcs(&verts[3 * i + 1]),
                                  __ldcs(&verts[3 * i + 2]), 0.0f);
        g_vns4[i]   = make_float4(__ldcs(&vns[3 * i]), __ldcs(&vns[3 * i + 1]),
                                  __ldcs(&vns[3 * i + 2]), 0.0f);
    } else {
        int j = idx * 256 + tid;
        if (j >= BF) return;
        const float* sp = fuvz + (size_t)j * 9;
        float4 o;
        o.x = 1.0f / __ldcs(&sp[2]);
        o.y = 1.0f / __ldcs(&sp[5]);
        o.z = 1.0f / __ldcs(&sp[8]);
        o.w = 0.0f;
        g_invfz[j] = o;
    }
}

// ---------- kernel 2: pack mixed-precision face records ---------------------
#define PF 64
__global__ __launch_bounds__(256) void pack_kernel(
        const float* __restrict__ vts,
        const int* __restrict__ f_vt,
        const int* __restrict__ f_vn,
        const int* __restrict__ f_v,
        int F) {
    __shared__ float s_f[PF * 16];           // PF x 64B records
    int tid = threadIdx.x;
    int fbase = blockIdx.x * PF;
    if (tid < PF * 3) {
        int gi = fbase * 3 + tid;            // coalesced corner index
        int fl = tid / 3, k = tid - fl * 3;
        bool ok = (fbase + fl) < F;
        int it  = ok ? __ldg(&f_vt[gi]) : 0;
        int in_ = ok ? __ldg(&f_vn[gi]) : 0;
        int iv  = ok ? __ldg(&f_v[gi])  : 0;
        float2 t2 = __ldg((const float2*)vts + it);
        float4 n4 = __ldg(&g_vns4[in_]);
        float4 v4 = __ldg(&g_verts4[iv]);
        float*  rf = s_f + fl * 16;
        __half* rh = (__half*)rf;
        rf[2 * k + 0] = t2.x;
        rf[2 * k + 1] = t2.y;
        rh[12 + 3 * k + 0] = __float2half_rn(n4.x);
        rh[12 + 3 * k + 1] = __float2half_rn(n4.y);
        rh[12 + 3 * k + 2] = __float2half_rn(n4.z);
        rh[21 + 3 * k + 0] = __float2half_rn(v4.x);
        rh[21 + 3 * k + 1] = __float2half_rn(v4.y);
        rh[21 + 3 * k + 2] = __float2half_rn(v4.z);
        if (k == 0) { rh[30] = __float2half_rn(0.f); rh[31] = __float2half_rn(0.f); }
    }
    __syncthreads();
    const uint4* s4 = (const uint4*)s_f;
    size_t di = (size_t)fbase * 4 + tid;     // PF*4 = 256 chunks/block
    if (di < (size_t)FMAX * 4)
        g_packed[di] = s4[tid];
}

// ---------- kernel 3: main per-pixel pass (2 px/thread, staged weight) ------
#define BLK 128
#define PPB 256   // pixels per block

__global__ __launch_bounds__(BLK) void raster_main_kernel(
        const int* __restrict__ fidx_map,
        const float* __restrict__ depth,
        const float* __restrict__ weight,
        const float* __restrict__ pose,
        float* __restrict__ out,
        int HW, int F, int total) {
    __shared__ float sm[PPB * 14];            // output staging (14336 B)
    __shared__ float smw[PPB * 3];            // staged weights (3072 B)

    int tid  = threadIdx.x;
    int base = blockIdx.x * PPB;
    int b    = base / HW;                     // uniform per block (PPB | HW)

    // Coalesced weight stage: 192 float4 = PPB*3 floats.
    {
        const float4* wg = (const float4*)(weight + (size_t)base * 3);
        size_t limit4 = ((size_t)total * 3 - (size_t)base * 3) / 4;
#pragma unroll
        for (int k = 0; k < 2; k++) {
            int e = k * BLK + tid;
            if (e < (PPB * 3) / 4 && (size_t)e < limit4)
                ((float4*)smw)[e] = __ldcs(&wg[e]);
        }
    }

    // pose once per thread (broadcast loads)
    const float* P = pose + b * 16;
    float R00 = __ldg(&P[0]), R01 = __ldg(&P[1]), R02 = __ldg(&P[2]),  t0 = __ldg(&P[3]);
    float R10 = __ldg(&P[4]), R11 = __ldg(&P[5]), R12 = __ldg(&P[6]),  t1 = __ldg(&P[7]);
    float R20 = __ldg(&P[8]), R21 = __ldg(&P[9]), R22 = __ldg(&P[10]), t2 = __ldg(&P[11]);

    // ---- front-batched divergent loads for both pixels (max MLP) ----
    int   gid[2];
    bool  act[2];
    int   f[2];
    float d[2];
    float4 iz[2];
    uint4 q0[2], q1[2], q2[2], q3[2];

#pragma unroll
    for (int s = 0; s < 2; s++) {
        gid[s] = base + s * BLK + tid;
        act[s] = (gid[s] < total);
        int g = act[s] ? gid[s] : 0;
        f[s]  = __ldcs(&fidx_map[g]);
        d[s]  = __ldcs(&depth[g]);
    }
#pragma unroll
    for (int s = 0; s < 2; s++) {
        iz[s] = __ldg(&g_invfz[b * F + f[s]]);
        const uint4* rec4 = g_packed + (size_t)f[s] * 4;
        q0[s] = __ldg(&rec4[0]);
        q1[s] = __ldg(&rec4[1]);
        q2[s] = __ldg(&rec4[2]);
        q3[s] = __ldg(&rec4[3]);
    }
    __syncthreads();   // weights staged

    // ---- compute + smem staging ----
#pragma unroll
    for (int s = 0; s < 2; s++) {
        float vals[14];
#pragma unroll
        for (int j = 0; j < 14; j++) vals[j] = 0.0f;

        if (act[s]) {
            int slot = s * BLK + tid;
            float w0 = smw[slot * 3 + 0];
            float w1 = smw[slot * 3 + 1];
            float w2 = smw[slot * 3 + 2];

            // fp32 vt: words 0..5
            float vt00 = __uint_as_float(q0[s].x);
            float vt01 = __uint_as_float(q0[s].y);
            float vt10 = __uint_as_float(q0[s].z);
            float vt11 = __uint_as_float(q0[s].w);
            float vt20 = __uint_as_float(q1[s].x);
            float vt21 = __uint_as_float(q1[s].y);

            // fp16 vn + v: words 6..15 -> 20 halves (18 used)
            float h[20];
            {
                unsigned int w[10] = {q1[s].z, q1[s].w,
                                      q2[s].x, q2[s].y, q2[s].z, q2[s].w,
                                      q3[s].x, q3[s].y, q3[s].z, q3[s].w};
#pragma unroll
                for (int i = 0; i < 10; i++) {
                    float2 f2 = __half22float2(*(const __half2*)&w[i]);
                    h[2 * i] = f2.x; h[2 * i + 1] = f2.y;
                }
            }

            float c0 = iz[s].x * w0 * d[s];
            float c1 = iz[s].y * w1 * d[s];
            float c2 = iz[s].z * w2 * d[s];

            // uv (full fp32)
            float u = vt00 * c0 + vt10 * c1 + vt20 * c2;
            float v = vt01 * c0 + vt11 * c1 + vt21 * c2;
            u = u - floorf(u);
            v = v - floorf(v);

            // normal blend + normalize
            float nx = h[0] * c0 + h[3] * c1 + h[6] * c2;
            float ny = h[1] * c0 + h[4] * c1 + h[7] * c2;
            float nz = h[2] * c0 + h[5] * c1 + h[8] * c2;
            float nl = sqrtf(nx * nx + ny * ny + nz * nz);
            float inl = 1.0f / fmaxf(nl, 1e-12f);
            float Nx = nx * inl, Ny = ny * inl, Nz = nz * inl;

            // position blend
            float px = h[9]  * c0 + h[12] * c1 + h[15] * c2;
            float py = h[10] * c0 + h[13] * c1 + h[16] * c2;
            float pz = h[11] * c0 + h[14] * c1 + h[17] * c2;

            float mx = R00 * Nx + R01 * Ny + R02 * Nz;
            float my = R10 * Nx + R11 * Ny + R12 * Nz;
            float mz = R20 * Nx + R21 * Ny + R22 * Nz;
            float ml = sqrtf(mx * mx + my * my + mz * mz);
            float iml = 1.0f / fmaxf(ml, 1e-12f);
            mx *= iml; my *= iml; mz *= iml;

            float qx = R00 * px + R01 * py + R02 * pz + t0;
            float qy = R10 * px + R11 * py + R12 * pz + t1;
            float qz = R20 * px + R21 * py + R22 * pz + t2;

            vals[0] = u;   vals[1] = v;
            vals[2] = Nx;  vals[3] = Ny;  vals[4] = Nz;
            vals[5] = mx;  vals[6] = my;  vals[7] = mz;
            vals[8] = px;  vals[9] = py;  vals[10] = pz;
            vals[11] = qx; vals[12] = qy; vals[13] = qz;
        }

        int slot = s * BLK + tid;
#pragma unroll
        for (int j = 0; j < 14; j++) sm[slot * 14 + j] = vals[j];
    }
    __syncthreads();

    // coalesced float4 streaming stores of the block's contiguous region
    size_t blk_base = (size_t)blockIdx.x * PPB * 14;
    const float4* sm4 = (const float4*)sm;
    float4* out4 = (float4*)(out + blk_base);
    int nfloat4 = (PPB * 14) / 4;                      // 896
    size_t limit4 = ((size_t)total * 14 - blk_base) / 4;
#pragma unroll
    for (int it = 0; it < 7; it++) {
        int e = it * BLK + tid;
        if (e < nfloat4 && (size_t)e < limit4)
            __stcs(&out4[e], sm4[e]);
    }
}

extern "C" void kernel_launch(void* const* d_in, const int* in_sizes, int n_in,
                              void* d_out, int out_size) {
    const float* vertices = (const float*)d_in[0];   // (1,V,3)
    const float* vt       = (const float*)d_in[1];   // (1,V,2)
    const float* vn       = (const float*)d_in[2];   // (1,V,3)
    const int*   f_vt     = (const int*)d_in[3];     // (1,F,3)
    const int*   f_vn     = (const int*)d_in[4];     // (1,F,3)
    const int*   f_v      = (const int*)d_in[5];     // (1,F,3)
    const float* pose     = (const float*)d_in[6];   // (B,4,4)
    const float* depth    = (const float*)d_in[7];   // (B,H,W)
    const int*   fim      = (const int*)d_in[8];     // (B,H,W)
    const float* wm       = (const float*)d_in[9];   // (B,H,W,3)
    // d_in[10] = v_uvz: dead code in reference
    const float* fuvz     = (const float*)d_in[11];  // (B,F,3,3)

    int V   = in_sizes[0] / 3;
    int F   = in_sizes[3] / 3;
    int B   = in_sizes[6] / 16;
    int BHW = in_sizes[7];
    int HW  = BHW / B;
    int BF  = B * F;

    int blocksE  = (V + 255) / 256;
    int blocksFZ = (BF + 255) / 256;
    int blocksF  = (F + PF - 1) / PF;

    expand_fz_kernel<<<blocksE + blocksFZ, 256>>>(vertices, vn, fuvz,
                                                  V, BF, blocksE, blocksFZ);
    pack_kernel<<<blocksF, 256>>>(vt, f_vt, f_vn, f_v, F);
    raster_main_kernel<<<(BHW + PPB - 1) / PPB, BLK>>>(fim, depth, wm, pose,
                                                       (float*)d_out, HW, F, BHW);
}

// round 17
// speedup vs baseline: 1.6301x; 1.6301x over previous
#include <cuda_runtime.h>
#include <cuda_fp16.h>
#include <math.h>

// Fixed problem shape: F=200000, B=4, V=100000.
#define FMAX 200000
#define BMAX 4
#define VMAX 100000

// Mixed-precision 64B per-face record (4 uint4 chunks), 128B-array-aligned.
// bytes  0..23 : vt as fp32  [vt0.u vt0.v vt1.u vt1.v vt2.u vt2.v]
// bytes 24..41 : vn as fp16  [vn0.xyz vn1.xyz vn2.xyz]   (half idx 12..20)
// bytes 42..59 : v  as fp16  [v0.xyz  v1.xyz  v2.xyz ]   (half idx 21..29)
// bytes 60..63 : pad                                      (half idx 30..31)
__device__ __align__(128) uint4 g_packed[FMAX * 4];
// Per (b,f): {1/z0, 1/z1, 1/z2, 0} fp32
__device__ float4 g_invfz[BMAX * FMAX];
// fp32-expanded vertex attribute tables (one LDG.128 per gather in pack)
__device__ float4 g_verts4[VMAX];
__device__ float4 g_vns4[VMAX];

// ---------- kernel 1: expand verts/vns (128-thread blocks for balance) ------
#define EBLK 128
__global__ __launch_bounds__(EBLK) void expand_kernel(
        const float* __restrict__ verts,
        const float* __restrict__ vns, int V) {
    int i = blockIdx.x * EBLK + threadIdx.x;
    if (i >= V) return;
    g_verts4[i] = make_float4(__ldcs(&verts[3 * i]), __ldcs(&verts[3 * i + 1]),
                              __ldcs(&verts[3 * i + 2]), 0.0f);
    g_vns4[i]   = make_float4(__ldcs(&vns[3 * i]), __ldcs(&vns[3 * i + 1]),
                              __ldcs(&vns[3 * i + 2]), 0.0f);
}

// ---------- kernel 2: pack (L1-bound) parity-interleaved with fz ------------
#define PF 64
__global__ __launch_bounds__(256) void pack_fz_kernel(
        const float* __restrict__ vts,
        const int* __restrict__ f_vt,
        const int* __restrict__ f_vn,
        const int* __restrict__ f_v,
        const float* __restrict__ fuvz,
        int F, int blocksF, int blocksFZ, int BF) {
    int tid = threadIdx.x;
    int bi  = blockIdx.x;
    int twice = 2 * (blocksF < blocksFZ ? blocksF : blocksFZ);
    bool isPack;
    int idx;
    if (bi < twice) { isPack = !(bi & 1); idx = bi >> 1; }
    else {
        int r = bi - twice;
        if (blocksF > blocksFZ) { isPack = true;  idx = blocksFZ + r; }
        else                    { isPack = false; idx = blocksF  + r; }
    }

    if (isPack) {
        __shared__ float s_f[PF * 16];           // PF x 64B records
        int fbase = idx * PF;
        if (tid < PF * 3) {
            int gi = fbase * 3 + tid;            // coalesced corner index
            int fl = tid / 3, k = tid - fl * 3;
            bool ok = (fbase + fl) < F;
            int it  = ok ? __ldg(&f_vt[gi]) : 0;
            int in_ = ok ? __ldg(&f_vn[gi]) : 0;
            int iv  = ok ? __ldg(&f_v[gi])  : 0;
            float2 t2 = __ldg((const float2*)vts + it);
            float4 n4 = __ldg(&g_vns4[in_]);
            float4 v4 = __ldg(&g_verts4[iv]);
            float*  rf = s_f + fl * 16;
            __half* rh = (__half*)rf;
            rf[2 * k + 0] = t2.x;
            rf[2 * k + 1] = t2.y;
            rh[12 + 3 * k + 0] = __float2half_rn(n4.x);
            rh[12 + 3 * k + 1] = __float2half_rn(n4.y);
            rh[12 + 3 * k + 2] = __float2half_rn(n4.z);
            rh[21 + 3 * k + 0] = __float2half_rn(v4.x);
            rh[21 + 3 * k + 1] = __float2half_rn(v4.y);
            rh[21 + 3 * k + 2] = __float2half_rn(v4.z);
            if (k == 0) { rh[30] = __float2half_rn(0.f); rh[31] = __float2half_rn(0.f); }
        }
        __syncthreads();
        const uint4* s4 = (const uint4*)s_f;
        size_t di = (size_t)fbase * 4 + tid;     // PF*4 = 256 chunks/block
        if (di < (size_t)FMAX * 4)
            g_packed[di] = s4[tid];
    } else {
        int j = idx * 256 + tid;
        if (j >= BF) return;
        const float* sp = fuvz + (size_t)j * 9;
        float4 o;
        o.x = 1.0f / __ldcs(&sp[2]);
        o.y = 1.0f / __ldcs(&sp[5]);
        o.z = 1.0f / __ldcs(&sp[8]);
        o.w = 0.0f;
        g_invfz[j] = o;
    }
}

// ---------- kernel 3: main per-pixel pass (2 px/thread, batched loads) ------
#define BLK 128
#define PPB 256   // pixels per block

__global__ __launch_bounds__(BLK) void raster_main_kernel(
        const int* __restrict__ fidx_map,
        const float* __restrict__ depth,
        const float* __restrict__ weight,
        const float* __restrict__ pose,
        float* __restrict__ out,
        int HW, int F, int total) {
    __shared__ float sm[PPB * 14];

    int tid  = threadIdx.x;
    int base = blockIdx.x * PPB;
    int b    = base / HW;                     // uniform per block (PPB | HW)

    // pose once per thread (broadcast loads)
    const float* P = pose + b * 16;
    float R00 = __ldg(&P[0]), R01 = __ldg(&P[1]), R02 = __ldg(&P[2]),  t0 = __ldg(&P[3]);
    float R10 = __ldg(&P[4]), R11 = __ldg(&P[5]), R12 = __ldg(&P[6]),  t1 = __ldg(&P[7]);
    float R20 = __ldg(&P[8]), R21 = __ldg(&P[9]), R22 = __ldg(&P[10]), t2 = __ldg(&P[11]);

    // ---- front-batched loads for both pixels (max MLP) ----
    int   gid[2];
    bool  act[2];
    int   f[2];
    float d[2], w0[2], w1[2], w2[2];
    float4 iz[2];
    uint4 q0[2], q1[2], q2[2], q3[2];

#pragma unroll
    for (int s = 0; s < 2; s++) {
        gid[s] = base + s * BLK + tid;
        act[s] = (gid[s] < total);
        int g = act[s] ? gid[s] : 0;
        f[s]  = __ldcs(&fidx_map[g]);
        d[s]  = __ldcs(&depth[g]);
        w0[s] = __ldcs(&weight[g * 3 + 0]);
        w1[s] = __ldcs(&weight[g * 3 + 1]);
        w2[s] = __ldcs(&weight[g * 3 + 2]);
    }
#pragma unroll
    for (int s = 0; s < 2; s++) {
        iz[s] = __ldg(&g_invfz[b * F + f[s]]);
        const uint4* rec4 = g_packed + (size_t)f[s] * 4;
        q0[s] = __ldg(&rec4[0]);
        q1[s] = __ldg(&rec4[1]);
        q2[s] = __ldg(&rec4[2]);
        q3[s] = __ldg(&rec4[3]);
    }

    // ---- compute + smem staging ----
#pragma unroll
    for (int s = 0; s < 2; s++) {
        float vals[14];
#pragma unroll
        for (int j = 0; j < 14; j++) vals[j] = 0.0f;

        if (act[s]) {
            // fp32 vt: words 0..5
            float vt00 = __uint_as_float(q0[s].x);
            float vt01 = __uint_as_float(q0[s].y);
            float vt10 = __uint_as_float(q0[s].z);
            float vt11 = __uint_as_float(q0[s].w);
            float vt20 = __uint_as_float(q1[s].x);
            float vt21 = __uint_as_float(q1[s].y);

            // fp16 vn + v: words 6..15 -> 20 halves (18 used)
            float h[20];
            {
                unsigned int w[10] = {q1[s].z, q1[s].w,
                                      q2[s].x, q2[s].y, q2[s].z, q2[s].w,
                                      q3[s].x, q3[s].y, q3[s].z, q3[s].w};
#pragma unroll
                for (int i = 0; i < 10; i++) {
                    float2 f2 = __half22float2(*(const __half2*)&w[i]);
                    h[2 * i] = f2.x; h[2 * i + 1] = f2.y;
                }
            }

            float c0 = iz[s].x * w0[s] * d[s];
            float c1 = iz[s].y * w1[s] * d[s];
            float c2 = iz[s].z * w2[s] * d[s];

            // uv (full fp32)
            float u = vt00 * c0 + vt10 * c1 + vt20 * c2;
            float v = vt01 * c0 + vt11 * c1 + vt21 * c2;
            u = u - floorf(u);
            v = v - floorf(v);

            // normal blend + normalize
            float nx = h[0] * c0 + h[3] * c1 + h[6] * c2;
            float ny = h[1] * c0 + h[4] * c1 + h[7] * c2;
            float nz = h[2] * c0 + h[5] * c1 + h[8] * c2;
            float nl = sqrtf(nx * nx + ny * ny + nz * nz);
            float inl = 1.0f / fmaxf(nl, 1e-12f);
            float Nx = nx * inl, Ny = ny * inl, Nz = nz * inl;

            // position blend
            float px = h[9]  * c0 + h[12] * c1 + h[15] * c2;
            float py = h[10] * c0 + h[13] * c1 + h[16] * c2;
            float pz = h[11] * c0 + h[14] * c1 + h[17] * c2;

            float mx = R00 * Nx + R01 * Ny + R02 * Nz;
            float my = R10 * Nx + R11 * Ny + R12 * Nz;
            float mz = R20 * Nx + R21 * Ny + R22 * Nz;
            float ml = sqrtf(mx * mx + my * my + mz * mz);
            float iml = 1.0f / fmaxf(ml, 1e-12f);
            mx *= iml; my *= iml; mz *= iml;

            float qx = R00 * px + R01 * py + R02 * pz + t0;
            float qy = R10 * px + R11 * py + R12 * pz + t1;
            float qz = R20 * px + R21 * py + R22 * pz + t2;

            vals[0] = u;   vals[1] = v;
            vals[2] = Nx;  vals[3] = Ny;  vals[4] = Nz;
            vals[5] = mx;  vals[6] = my;  vals[7] = mz;
            vals[8] = px;  vals[9] = py;  vals[10] = pz;
            vals[11] = qx; vals[12] = qy; vals[13] = qz;
        }

        int slot = s * BLK + tid;
#pragma unroll
        for (int j = 0; j < 14; j++) sm[slot * 14 + j] = vals[j];
    }
    __syncthreads();

    // coalesced float4 streaming stores of the block's contiguous region
    size_t blk_base = (size_t)blockIdx.x * PPB * 14;
    const float4* sm4 = (const float4*)sm;
    float4* out4 = (float4*)(out + blk_base);
    int nfloat4 = (PPB * 14) / 4;                      // 896
    size_t limit4 = ((size_t)total * 14 - blk_base) / 4;
#pragma unroll
    for (int it = 0; it < 7; it++) {
        int e = it * BLK + tid;
        if (e < nfloat4 && (size_t)e < limit4)
            __stcs(&out4[e], sm4[e]);
    }
}

extern "C" void kernel_launch(void* const* d_in, const int* in_sizes, int n_in,
                              void* d_out, int out_size) {
    const float* vertices = (const float*)d_in[0];   // (1,V,3)
    const float* vt       = (const float*)d_in[1];   // (1,V,2)
    const float* vn       = (const float*)d_in[2];   // (1,V,3)
    const int*   f_vt     = (const int*)d_in[3];     // (1,F,3)
    const int*   f_vn     = (const int*)d_in[4];     // (1,F,3)
    const int*   f_v      = (const int*)d_in[5];     // (1,F,3)
    const float* pose     = (const float*)d_in[6];   // (B,4,4)
    const float* depth    = (const float*)d_in[7];   // (B,H,W)
    const int*   fim      = (const int*)d_in[8];     // (B,H,W)
    const float* wm       = (const float*)d_in[9];   // (B,H,W,3)
    // d_in[10] = v_uvz: dead code in reference
    const float* fuvz     = (const float*)d_in[11];  // (B,F,3,3)

    int V   = in_sizes[0] / 3;
    int F   = in_sizes[3] / 3;
    int B   = in_sizes[6] / 16;
    int BHW = in_sizes[7];
    int HW  = BHW / B;
    int BF  = B * F;

    int blocksF  = (F + PF - 1) / PF;
    int blocksFZ = (BF + 255) / 256;

    expand_kernel<<<(V + EBLK - 1) / EBLK, EBLK>>>(vertices, vn, V);
    pack_fz_kernel<<<blocksF + blocksFZ, 256>>>(vt, f_vt, f_vn, f_v, fuvz,
                                                F, blocksF, blocksFZ, BF);
    raster_main_kernel<<<(BHW + PPB - 1) / PPB, BLK>>>(fim, depth, wm, pose,
                                                       (float*)d_out, HW, F, BHW);
}